// round 12
// baseline (speedup 1.0000x reference)
#include <cuda_runtime.h>
#include <math.h>

// ---------------- problem constants ----------------
#define BATCH   16
#define SLEN    512
#define DIM     512
#define VOCAB   32000
#define KBEAM   4
#define TMAX    64
#define SOS_TOK 1
#define EOS_TOK 2
#define PAD_TOK 0
#define NEGV    (-1e9f)
#define ATT_SCALE 0.044194173824159216f   // 1/sqrt(512)

#define BN     128
#define VBLKS  (VOCAB / BN)   // 250
#define BKC    128            // K-chunk for A staging
#define NBLK_LOGITS (VBLKS * 2)   // 500 blocks (2 row-groups)

// ---------------- persistent scratch ----------------
__device__ float g_encK[(size_t)BATCH * SLEN * DIM];    // row-major [b][s][d]
__device__ float g_q[64 * DIM];
__device__ float g_att[64 * SLEN];
__device__ float g_h[64 * DIM];
__device__ unsigned long long g_pkey[64][VBLKS][4];
__device__ float g_pm[64][VBLKS];
__device__ float g_ps[64][VBLKS];
__device__ float g_scores[64];
__device__ int   g_fin[64];
__device__ int   g_cur[64];
__device__ int   g_seqs[64 * TMAX];
__device__ int   g_count;

// ---------------- key encoding: (value desc, index asc) total order ----------------
__device__ __forceinline__ unsigned long long enc_key(float v, int idx) {
    unsigned u = __float_as_uint(v);
    u = (u & 0x80000000u) ? ~u : (u | 0x80000000u);
    return ((unsigned long long)u << 32) | (unsigned)(0xffffffffu - (unsigned)idx);
}
__device__ __forceinline__ float dec_val(unsigned long long k) {
    unsigned u = (unsigned)(k >> 32);
    u = (u & 0x80000000u) ? (u ^ 0x80000000u) : ~u;
    return __uint_as_float(u);
}
__device__ __forceinline__ int dec_idx(unsigned long long k) {
    return (int)(0xffffffffu - (unsigned)(k & 0xffffffffull));
}
__device__ __forceinline__ void kswap(unsigned long long &a, unsigned long long &b) {
    unsigned long long mx = a > b ? a : b;
    unsigned long long mn = a > b ? b : a;
    a = mx; b = mn;
}
#define MERGE44(k0,k1,k2,k3,b0,b1,b2,b3) do {            \
    unsigned long long c4=(b3), c5=(b2), c6=(b1), c7=(b0); \
    kswap(k0,c4); kswap(k1,c5); kswap(k2,c6); kswap(k3,c7); \
    kswap(k0,k2); kswap(k1,k3); kswap(k0,k1); kswap(k2,k3); \
} while(0)

// ---------------- encK GEMM (one-time): C[b*S+s][d] ----------------
#define GBM 64
#define GBN 128
#define GBK 32
__global__ __launch_bounds__(256) void sgemm_kernel(
    const float* __restrict__ A, const float* __restrict__ B,
    float* __restrict__ C, int M, int N, int K)
{
    __shared__ float As[GBK][GBM];
    __shared__ float Bs[GBK][GBN];
    const int tid = threadIdx.x;
    const int tx  = tid & 31;
    const int ty  = tid >> 5;
    const int m0  = blockIdx.y * GBM;
    const int n0  = blockIdx.x * GBN;
    float acc[8][4];
#pragma unroll
    for (int i = 0; i < 8; i++)
#pragma unroll
        for (int j = 0; j < 4; j++) acc[i][j] = 0.f;
    for (int k0 = 0; k0 < K; k0 += GBK) {
#pragma unroll
        for (int i = 0; i < 8; i++) {
            int l = tid + i * 256;
            int m = l >> 5, k = l & 31;
            As[k][m] = A[(size_t)(m0 + m) * K + (k0 + k)];
        }
#pragma unroll
        for (int i = 0; i < 16; i++) {
            int l = tid + i * 256;
            int k = l >> 7, n = l & 127;
            Bs[k][n] = B[(size_t)(k0 + k) * N + (n0 + n)];
        }
        __syncthreads();
#pragma unroll
        for (int k = 0; k < GBK; k++) {
            float4 bv = *(const float4*)&Bs[k][tx * 4];
#pragma unroll
            for (int i = 0; i < 8; i++) {
                float av = As[k][ty * 8 + i];
                acc[i][0] += av * bv.x; acc[i][1] += av * bv.y;
                acc[i][2] += av * bv.z; acc[i][3] += av * bv.w;
            }
        }
        __syncthreads();
    }
    const int n = n0 + tx * 4;
#pragma unroll
    for (int i = 0; i < 8; i++) {
        int m = m0 + ty * 8 + i;
        float4 r; r.x = acc[i][0]; r.y = acc[i][1]; r.z = acc[i][2]; r.w = acc[i][3];
        *(float4*)&C[(size_t)m * N + n] = r;
    }
}

// ---------------- attn phase A: q = e @ Wq, one col per thread (round-5 exact) ----------------
__global__ __launch_bounds__(512) void q_kernel(
    const float* __restrict__ emb, const float* __restrict__ Wq, int t)
{
    __shared__ float e_s[DIM];
    const int row = blockIdx.x;
    const int tid = threadIdx.x;
    const int tok = (t == 1) ? SOS_TOK : g_cur[row];
    e_s[tid] = emb[(size_t)tok * DIM + tid];
    __syncthreads();
    float a = 0.f;
    const float* wp = Wq + tid;
#pragma unroll 8
    for (int d = 0; d < DIM; d++) { a += e_s[d] * wp[0]; wp += DIM; }
    g_q[row * DIM + tid] = a;
}

// ---------------- attn phase B: scores, warp per s (round-5 exact) ----------------
__global__ __launch_bounds__(256) void score_kernel(const int* __restrict__ lens)
{
    const int row   = blockIdx.x;
    const int chunk = blockIdx.y;
    const int b     = row >> 2;
    const int tid   = threadIdx.x;
    const int lane  = tid & 31;
    const int w     = tid >> 5;
    const int len   = lens[b];

    float4 qv[4];
#pragma unroll
    for (int j = 0; j < 4; j++)
        qv[j] = *(const float4*)&g_q[row * DIM + (j * 32 + lane) * 4];

    for (int ss = 0; ss < 8; ss++) {
        const int s = chunk * 64 + w * 8 + ss;
        const float4* ek = (const float4*)(g_encK + (((size_t)b * SLEN + s) << 9));
        float acc = 0.f;
#pragma unroll
        for (int j = 0; j < 4; j++) {
            float4 kv = ek[j * 32 + lane];
            acc += qv[j].x * kv.x + qv[j].y * kv.y + qv[j].z * kv.z + qv[j].w * kv.w;
        }
#pragma unroll
        for (int off = 16; off; off >>= 1) acc += __shfl_xor_sync(0xffffffffu, acc, off);
        if (lane == 0) g_att[row * SLEN + s] = (s < len) ? acc * ATT_SCALE : NEGV;
    }
}

// ---------------- attn phase C: softmax (round-5 exact tree), in-place ----------------
__global__ __launch_bounds__(256) void softmax_kernel()
{
    __shared__ float red[256];
    const int row = blockIdx.x;
    const int tid = threadIdx.x;

    float v0 = g_att[row * SLEN + tid];
    float v1 = g_att[row * SLEN + tid + 256];
    red[tid] = fmaxf(v0, v1);
    __syncthreads();
    for (int off = 128; off > 0; off >>= 1) {
        if (tid < off) red[tid] = fmaxf(red[tid], red[tid + off]);
        __syncthreads();
    }
    const float mx = red[0];
    __syncthreads();
    float p0 = __expf(v0 - mx);
    float p1 = __expf(v1 - mx);
    red[tid] = p0 + p1;
    __syncthreads();
    for (int off = 128; off > 0; off >>= 1) {
        if (tid < off) red[tid] += red[tid + off];
        __syncthreads();
    }
    const float inv = 1.0f / red[0];
    g_att[row * SLEN + tid]       = p0 * inv;
    g_att[row * SLEN + tid + 256] = p1 * inv;
}

// ---------------- attn phase D: ctx + h, beam-shared enc loads, deep MLP ----------------
__global__ __launch_bounds__(64) void ctx2_kernel(
    const float* __restrict__ enc, const float* __restrict__ emb, int t)
{
    __shared__ float p_s[4][SLEN];   // 8 KB
    const int b   = blockIdx.x;
    const int c   = blockIdx.y;
    const int tid = threadIdx.x;
    const int d   = c * 64 + tid;

    for (int i = tid; i < 4 * SLEN; i += 64)
        p_s[i >> 9][i & 511] = g_att[(b * 4 + (i >> 9)) * SLEN + (i & 511)];
    __syncthreads();

    float a0 = 0.f, a1 = 0.f, a2 = 0.f, a3 = 0.f;
    const float* eb = enc + (size_t)b * SLEN * DIM + d;

    for (int s = 0; s < SLEN; s += 16) {
        float ev[16];
#pragma unroll
        for (int j = 0; j < 16; j++) ev[j] = eb[(size_t)(s + j) * DIM];
#pragma unroll
        for (int j = 0; j < 16; j++) {
            a0 += p_s[0][s + j] * ev[j];
            a1 += p_s[1][s + j] * ev[j];
            a2 += p_s[2][s + j] * ev[j];
            a3 += p_s[3][s + j] * ev[j];
        }
    }

    float acc[4] = {a0, a1, a2, a3};
#pragma unroll
    for (int k = 0; k < 4; k++) {
        const int row = b * 4 + k;
        const int tok = (t == 1) ? SOS_TOK : g_cur[row];
        g_h[row * DIM + d] = emb[(size_t)tok * DIM + d] + acc[k];
    }
}

// ---------------- fused logits GEMM (prefetch-8 B loads) + top4/LSE + beam combine ----------------
__global__ __launch_bounds__(256) void logits_kernel(
    const float* __restrict__ Wfc, const float* __restrict__ bfc,
    float* __restrict__ out, int t)
{
    __shared__ float As[32][BKC];                       // 16 KB
    __shared__ unsigned long long s_ckey[4][64][4];     // 8 KB
    __shared__ float s_cm[4][64], s_cs[4][64];          // 2 KB
    __shared__ float s_lp[64][4];                       // 1 KB
    __shared__ int   s_tok[64][4];                      // 1 KB
    __shared__ int   s_last;

    const int tid = threadIdx.x;
    const int tx  = tid & 31;
    const int ty  = tid >> 5;        // 0..7, rows ty*4 .. ty*4+3 (local)
    const int cb  = blockIdx.x;      // column block 0..249
    const int rg  = blockIdx.y;      // row group 0..1
    const int n0  = cb * BN;
    const int n   = n0 + tx * 4;

    float acc[4][4];
#pragma unroll
    for (int i = 0; i < 4; i++)
#pragma unroll
        for (int j = 0; j < 4; j++) acc[i][j] = 0.f;

    // ---- GEMM: per-column k-chain sequential 0..511 (bit-exact); B loads batched 8 ahead ----
    for (int kc = 0; kc < DIM / BKC; kc++) {
#pragma unroll
        for (int i = 0; i < 4; i++) {
            int f  = tid + i * 256;              // 0..1023
            int m  = f >> 5;                     // 0..31
            int k4 = (f & 31) << 2;
            *(float4*)&As[m][k4] =
                *(const float4*)&g_h[(rg * 32 + m) * DIM + kc * BKC + k4];
        }
        __syncthreads();
        const float* Bp = Wfc + (size_t)(kc * BKC) * VOCAB + n;
        for (int kk = 0; kk < BKC; kk += 8) {
            float4 bv[8];
#pragma unroll
            for (int j = 0; j < 8; j++) { bv[j] = *(const float4*)Bp; Bp += VOCAB; }
#pragma unroll
            for (int i = 0; i < 4; i++) {
                float4 av0 = *(const float4*)&As[ty * 4 + i][kk];
                float4 av1 = *(const float4*)&As[ty * 4 + i][kk + 4];
                acc[i][0] += av0.x * bv[0].x; acc[i][1] += av0.x * bv[0].y;
                acc[i][2] += av0.x * bv[0].z; acc[i][3] += av0.x * bv[0].w;
                acc[i][0] += av0.y * bv[1].x; acc[i][1] += av0.y * bv[1].y;
                acc[i][2] += av0.y * bv[1].z; acc[i][3] += av0.y * bv[1].w;
                acc[i][0] += av0.z * bv[2].x; acc[i][1] += av0.z * bv[2].y;
                acc[i][2] += av0.z * bv[2].z; acc[i][3] += av0.z * bv[2].w;
                acc[i][0] += av0.w * bv[3].x; acc[i][1] += av0.w * bv[3].y;
                acc[i][2] += av0.w * bv[3].z; acc[i][3] += av0.w * bv[3].w;
                acc[i][0] += av1.x * bv[4].x; acc[i][1] += av1.x * bv[4].y;
                acc[i][2] += av1.x * bv[4].z; acc[i][3] += av1.x * bv[4].w;
                acc[i][0] += av1.y * bv[5].x; acc[i][1] += av1.y * bv[5].y;
                acc[i][2] += av1.y * bv[5].z; acc[i][3] += av1.y * bv[5].w;
                acc[i][0] += av1.z * bv[6].x; acc[i][1] += av1.z * bv[6].y;
                acc[i][2] += av1.z * bv[6].z; acc[i][3] += av1.z * bv[6].w;
                acc[i][0] += av1.w * bv[7].x; acc[i][1] += av1.w * bv[7].y;
                acc[i][2] += av1.w * bv[7].z; acc[i][3] += av1.w * bv[7].w;
            }
        }
        __syncthreads();
    }

    // ---- epilogue: per-row top4 + (max,sumexp) warp butterfly ----
    float4 bb = *(const float4*)&bfc[n];
#pragma unroll
    for (int i = 0; i < 4; i++) {
        const int r = rg * 32 + ty * 4 + i;
        float x0 = acc[i][0] + bb.x, x1 = acc[i][1] + bb.y;
        float x2 = acc[i][2] + bb.z, x3 = acc[i][3] + bb.w;
        float ml = fmaxf(fmaxf(x0, x1), fmaxf(x2, x3));
        float sl = __expf(x0 - ml) + __expf(x1 - ml) + __expf(x2 - ml) + __expf(x3 - ml);
        unsigned long long k0 = enc_key(x0, n);
        unsigned long long k1 = enc_key(x1, n + 1);
        unsigned long long k2 = enc_key(x2, n + 2);
        unsigned long long k3 = enc_key(x3, n + 3);
        kswap(k0, k1); kswap(k2, k3); kswap(k0, k2); kswap(k1, k3); kswap(k1, k2);
#pragma unroll
        for (int off = 16; off; off >>= 1) {
            unsigned long long b0 = __shfl_xor_sync(0xffffffffu, k0, off);
            unsigned long long b1 = __shfl_xor_sync(0xffffffffu, k1, off);
            unsigned long long b2 = __shfl_xor_sync(0xffffffffu, k2, off);
            unsigned long long b3 = __shfl_xor_sync(0xffffffffu, k3, off);
            MERGE44(k0, k1, k2, k3, b0, b1, b2, b3);
            float m2 = __shfl_xor_sync(0xffffffffu, ml, off);
            float s2 = __shfl_xor_sync(0xffffffffu, sl, off);
            float M = fmaxf(ml, m2);
            sl = sl * __expf(ml - M) + s2 * __expf(m2 - M);
            ml = M;
        }
        if (tx == 0) {
            g_pkey[r][cb][0] = k0; g_pkey[r][cb][1] = k1;
            g_pkey[r][cb][2] = k2; g_pkey[r][cb][3] = k3;
            g_pm[r][cb] = ml; g_ps[r][cb] = sl;
        }
    }

    // ---- last-block election ----
    __threadfence();
    __syncthreads();
    if (tid == 0) s_last = (atomicAdd(&g_count, 1) == NBLK_LOGITS - 1);
    __syncthreads();
    if (!s_last) return;
    __threadfence();

    // ---- merge 250 partials per row ----
    {
        const int r = tid & 63, c = tid >> 6;
        const int p0c = c * 64;
        const int p1c = (p0c + 64 < VBLKS) ? p0c + 64 : VBLKS;
        unsigned long long k0 = 0, k1 = 0, k2 = 0, k3 = 0;
        float m = -INFINITY, s = 0.f;
        for (int p = p0c; p < p1c; p++) {
            unsigned long long b0 = g_pkey[r][p][0], b1 = g_pkey[r][p][1];
            unsigned long long b2 = g_pkey[r][p][2], b3 = g_pkey[r][p][3];
            MERGE44(k0, k1, k2, k3, b0, b1, b2, b3);
            float m2 = g_pm[r][p], s2 = g_ps[r][p];
            float M = fmaxf(m, m2);
            s = s * __expf(m - M) + s2 * __expf(m2 - M);
            m = M;
        }
        s_ckey[c][r][0] = k0; s_ckey[c][r][1] = k1;
        s_ckey[c][r][2] = k2; s_ckey[c][r][3] = k3;
        s_cm[c][r] = m; s_cs[c][r] = s;
    }
    __syncthreads();
    if (tid < 64) {
        const int r = tid;
        unsigned long long k0 = s_ckey[0][r][0], k1 = s_ckey[0][r][1];
        unsigned long long k2 = s_ckey[0][r][2], k3 = s_ckey[0][r][3];
        float m = s_cm[0][r], s = s_cs[0][r];
#pragma unroll
        for (int c = 1; c < 4; c++) {
            unsigned long long b0 = s_ckey[c][r][0], b1 = s_ckey[c][r][1];
            unsigned long long b2 = s_ckey[c][r][2], b3 = s_ckey[c][r][3];
            MERGE44(k0, k1, k2, k3, b0, b1, b2, b3);
            float m2 = s_cm[c][r], s2 = s_cs[c][r];
            float M = fmaxf(m, m2);
            s = s * __expf(m - M) + s2 * __expf(m2 - M);
            m = M;
        }
        float lse = m + logf(s);
        s_lp[r][0] = dec_val(k0) - lse; s_tok[r][0] = dec_idx(k0);
        s_lp[r][1] = dec_val(k1) - lse; s_tok[r][1] = dec_idx(k1);
        s_lp[r][2] = dec_val(k2) - lse; s_tok[r][2] = dec_idx(k2);
        s_lp[r][3] = dec_val(k3) - lse; s_tok[r][3] = dec_idx(k3);
    }
    __syncthreads();

    // ---- beam init / combine (16 threads, one per batch) ----
    if (tid < 16) {
        const int b = tid;
        if (t == 1) {
            for (int k = 0; k < KBEAM; k++) {
                float lp = s_lp[b * 4][k];
                int   tk = s_tok[b * 4][k];
                g_scores[b * 4 + k] = lp;
                g_fin[b * 4 + k]    = (tk == EOS_TOK) ? 1 : 0;
                g_cur[b * 4 + k]    = tk;
                for (int pos = 0; pos < TMAX; pos++) {
                    int v2 = PAD_TOK;
                    if (pos == 0) v2 = SOS_TOK;
                    else if (pos == 1) v2 = tk;
                    g_seqs[(b * 4 + k) * TMAX + pos] = v2;
                }
            }
        } else {
            float sc[4]; int fin[4];
            for (int k = 0; k < 4; k++) {
                sc[k]  = g_scores[b * 4 + k];
                fin[k] = g_fin[b * 4 + k];
            }
            float tot[16]; int tokc[16];
            for (int k = 0; k < 4; k++) {
                for (int j = 0; j < 4; j++) {
                    float lp; int tk;
                    if (fin[k]) { lp = (j == 0) ? 0.f : NEGV; tk = PAD_TOK; }
                    else        { lp = s_lp[b * 4 + k][j]; tk = s_tok[b * 4 + k][j]; }
                    tot[k * 4 + j]  = sc[k] + lp;
                    tokc[k * 4 + j] = tk;
                }
            }
            int used[16];
            for (int i = 0; i < 16; i++) used[i] = 0;
            int selb[4], selt[4]; float selsc[4];
            for (int p = 0; p < 4; p++) {
                int best = -1; float bv = -INFINITY;
                for (int i = 0; i < 16; i++)
                    if (!used[i] && tot[i] > bv) { bv = tot[i]; best = i; }
                used[best] = 1;
                selsc[p] = bv;
                selb[p]  = best >> 2;
                selt[p]  = tokc[best];
            }
            int oldseq[4][TMAX];
            for (int k = 0; k < 4; k++)
                for (int pos = 0; pos < TMAX; pos++)
                    oldseq[k][pos] = g_seqs[(b * 4 + k) * TMAX + pos];
            for (int p = 0; p < 4; p++) {
                int bi = selb[p], tk = selt[p];
                for (int pos = 0; pos < TMAX; pos++)
                    g_seqs[(b * 4 + p) * TMAX + pos] = (pos == t) ? tk : oldseq[bi][pos];
                g_fin[b * 4 + p]    = fin[bi] | (tk == EOS_TOK);
                g_cur[b * 4 + p]    = tk;
                g_scores[b * 4 + p] = selsc[p];
            }
            if (t == TMAX - 1) {
                float bv = -INFINITY; int bi = 0;
                for (int k = 0; k < KBEAM; k++) {
                    float v2 = g_scores[b * 4 + k];
                    if (v2 > bv) { bv = v2; bi = k; }
                }
                for (int pos = 0; pos < TMAX; pos++)
                    out[b * TMAX + pos] = (float)g_seqs[(b * 4 + bi) * TMAX + pos];
                out[BATCH * TMAX + b] = bv;
            }
        }
    }
    if (tid == 0) g_count = 0;
}

// ---------------- launch ----------------
extern "C" void kernel_launch(void* const* d_in, const int* in_sizes, int n_in,
                              void* d_out, int out_size)
{
    const float* enc  = (const float*)d_in[0];
    const int*   lens = (const int*)  d_in[1];
    const float* emb  = (const float*)d_in[2];
    const float* Wq   = (const float*)d_in[3];
    const float* Wk   = (const float*)d_in[4];
    const float* Wfc  = (const float*)d_in[5];
    const float* bfc  = (const float*)d_in[6];
    float* out = (float*)d_out;

    float* p_encK;
    cudaGetSymbolAddress((void**)&p_encK, g_encK);

    // encK = enc @ Wk : [b][s][d] row-major
    sgemm_kernel<<<dim3(DIM / GBN, (BATCH * SLEN) / GBM), 256>>>(
        enc, Wk, p_encK, BATCH * SLEN, DIM, DIM);

    for (int t = 1; t < TMAX; t++) {
        q_kernel<<<64, 512>>>(emb, Wq, t);
        score_kernel<<<dim3(64, 8), 256>>>(lens);
        softmax_kernel<<<64, 256>>>();
        ctx2_kernel<<<dim3(16, 8), 64>>>(enc, emb, t);
        logits_kernel<<<dim3(VBLKS, 2), 256>>>(Wfc, bfc, out, t);
    }
}

// round 14
// speedup vs baseline: 1.2431x; 1.2431x over previous
#include <cuda_runtime.h>
#include <math.h>

// ---------------- problem constants ----------------
#define BATCH   16
#define SLEN    512
#define DIM     512
#define VOCAB   32000
#define KBEAM   4
#define TMAX    64
#define SOS_TOK 1
#define EOS_TOK 2
#define PAD_TOK 0
#define NEGV    (-1e9f)
#define ATT_SCALE 0.044194173824159216f   // 1/sqrt(512)

#define BN     128
#define VBLKS  (VOCAB / BN)   // 250
#define BKC    128            // K-chunk for A staging
#define NBLK_LOGITS (VBLKS * 2)   // 500 blocks (2 row-groups)

// ---------------- persistent scratch ----------------
__device__ float g_encK[(size_t)BATCH * SLEN * DIM];    // row-major [b][s][d]
__device__ float g_q[64 * DIM];
__device__ float g_att[64 * SLEN];                      // raw masked scores
__device__ float g_h[64 * DIM];
__device__ unsigned long long g_pkey[64][VBLKS][4];
__device__ float g_pm[64][VBLKS];
__device__ float g_ps[64][VBLKS];
__device__ float g_scores[64];
__device__ int   g_fin[64];
__device__ int   g_cur[64];
__device__ int   g_seqs[64 * TMAX];
__device__ int   g_count;

// ---------------- key encoding: (value desc, index asc) total order ----------------
__device__ __forceinline__ unsigned long long enc_key(float v, int idx) {
    unsigned u = __float_as_uint(v);
    u = (u & 0x80000000u) ? ~u : (u | 0x80000000u);
    return ((unsigned long long)u << 32) | (unsigned)(0xffffffffu - (unsigned)idx);
}
__device__ __forceinline__ float dec_val(unsigned long long k) {
    unsigned u = (unsigned)(k >> 32);
    u = (u & 0x80000000u) ? (u ^ 0x80000000u) : ~u;
    return __uint_as_float(u);
}
__device__ __forceinline__ int dec_idx(unsigned long long k) {
    return (int)(0xffffffffu - (unsigned)(k & 0xffffffffull));
}
__device__ __forceinline__ void kswap(unsigned long long &a, unsigned long long &b) {
    unsigned long long mx = a > b ? a : b;
    unsigned long long mn = a > b ? b : a;
    a = mx; b = mn;
}
#define MERGE44(k0,k1,k2,k3,b0,b1,b2,b3) do {            \
    unsigned long long c4=(b3), c5=(b2), c6=(b1), c7=(b0); \
    kswap(k0,c4); kswap(k1,c5); kswap(k2,c6); kswap(k3,c7); \
    kswap(k0,k2); kswap(k1,k3); kswap(k0,k1); kswap(k2,k3); \
} while(0)

// ---------------- encK GEMM (one-time): C[b*S+s][d] ----------------
#define GBM 64
#define GBN 128
#define GBK 32
__global__ __launch_bounds__(256) void sgemm_kernel(
    const float* __restrict__ A, const float* __restrict__ B,
    float* __restrict__ C, int M, int N, int K)
{
    __shared__ float As[GBK][GBM];
    __shared__ float Bs[GBK][GBN];
    const int tid = threadIdx.x;
    const int tx  = tid & 31;
    const int ty  = tid >> 5;
    const int m0  = blockIdx.y * GBM;
    const int n0  = blockIdx.x * GBN;
    float acc[8][4];
#pragma unroll
    for (int i = 0; i < 8; i++)
#pragma unroll
        for (int j = 0; j < 4; j++) acc[i][j] = 0.f;
    for (int k0 = 0; k0 < K; k0 += GBK) {
#pragma unroll
        for (int i = 0; i < 8; i++) {
            int l = tid + i * 256;
            int m = l >> 5, k = l & 31;
            As[k][m] = A[(size_t)(m0 + m) * K + (k0 + k)];
        }
#pragma unroll
        for (int i = 0; i < 16; i++) {
            int l = tid + i * 256;
            int k = l >> 7, n = l & 127;
            Bs[k][n] = B[(size_t)(k0 + k) * N + (n0 + n)];
        }
        __syncthreads();
#pragma unroll
        for (int k = 0; k < GBK; k++) {
            float4 bv = *(const float4*)&Bs[k][tx * 4];
#pragma unroll
            for (int i = 0; i < 8; i++) {
                float av = As[k][ty * 8 + i];
                acc[i][0] += av * bv.x; acc[i][1] += av * bv.y;
                acc[i][2] += av * bv.z; acc[i][3] += av * bv.w;
            }
        }
        __syncthreads();
    }
    const int n = n0 + tx * 4;
#pragma unroll
    for (int i = 0; i < 8; i++) {
        int m = m0 + ty * 8 + i;
        float4 r; r.x = acc[i][0]; r.y = acc[i][1]; r.z = acc[i][2]; r.w = acc[i][3];
        *(float4*)&C[(size_t)m * N + n] = r;
    }
}

// ---------------- attn phase A: q = e @ Wq, one col per thread (round-5 exact) ----------------
__global__ __launch_bounds__(512) void q_kernel(
    const float* __restrict__ emb, const float* __restrict__ Wq, int t)
{
    __shared__ float e_s[DIM];
    const int row = blockIdx.x;
    const int tid = threadIdx.x;
    const int tok = (t == 1) ? SOS_TOK : g_cur[row];
    e_s[tid] = emb[(size_t)tok * DIM + tid];
    __syncthreads();
    float a = 0.f;
    const float* wp = Wq + tid;
#pragma unroll 8
    for (int d = 0; d < DIM; d++) { a += e_s[d] * wp[0]; wp += DIM; }
    g_q[row * DIM + tid] = a;
}

// ---------------- attn phase B: scores, warp per s (round-5 exact) ----------------
__global__ __launch_bounds__(256) void score_kernel(const int* __restrict__ lens)
{
    const int row   = blockIdx.x;
    const int chunk = blockIdx.y;
    const int b     = row >> 2;
    const int tid   = threadIdx.x;
    const int lane  = tid & 31;
    const int w     = tid >> 5;
    const int len   = lens[b];

    float4 qv[4];
#pragma unroll
    for (int j = 0; j < 4; j++)
        qv[j] = *(const float4*)&g_q[row * DIM + (j * 32 + lane) * 4];

    for (int ss = 0; ss < 8; ss++) {
        const int s = chunk * 64 + w * 8 + ss;
        const float4* ek = (const float4*)(g_encK + (((size_t)b * SLEN + s) << 9));
        float acc = 0.f;
#pragma unroll
        for (int j = 0; j < 4; j++) {
            float4 kv = ek[j * 32 + lane];
            acc += qv[j].x * kv.x + qv[j].y * kv.y + qv[j].z * kv.z + qv[j].w * kv.w;
        }
#pragma unroll
        for (int off = 16; off; off >>= 1) acc += __shfl_xor_sync(0xffffffffu, acc, off);
        if (lane == 0) g_att[row * SLEN + s] = (s < len) ? acc * ATT_SCALE : NEGV;
    }
}

// ---------------- attn phase C+D fused: softmax (round-5 exact tree) + ctx + h ----------------
// grid (16 batches, 8 d-chunks) x 256 threads.
// Softmax: per beam, the exact 256-thread tree from the passing kernels (results to smem).
// Ctx: thread = (beam, d_local); chain a += p[s]*enc[b][s][d], s = 0..511 ascending (bit-exact).
__global__ __launch_bounds__(256) void sctx_kernel(
    const float* __restrict__ enc, const float* __restrict__ emb, int t)
{
    __shared__ float p_s[4][SLEN];   // 8 KB
    __shared__ float red[256];
    const int b   = blockIdx.x;
    const int c   = blockIdx.y;
    const int tid = threadIdx.x;

    // softmax for the 4 beams of batch b (round-5 exact arithmetic per beam)
    for (int k = 0; k < 4; k++) {
        const int row = b * 4 + k;
        float v0 = g_att[row * SLEN + tid];
        float v1 = g_att[row * SLEN + tid + 256];
        red[tid] = fmaxf(v0, v1);
        __syncthreads();
        for (int off = 128; off > 0; off >>= 1) {
            if (tid < off) red[tid] = fmaxf(red[tid], red[tid + off]);
            __syncthreads();
        }
        const float mx = red[0];
        __syncthreads();
        float p0 = __expf(v0 - mx);
        float p1 = __expf(v1 - mx);
        red[tid] = p0 + p1;
        __syncthreads();
        for (int off = 128; off > 0; off >>= 1) {
            if (tid < off) red[tid] += red[tid + off];
            __syncthreads();
        }
        const float inv = 1.0f / red[0];
        __syncthreads();
        p_s[k][tid]       = p0 * inv;
        p_s[k][tid + 256] = p1 * inv;
        __syncthreads();
    }

    // ctx: thread handles (beam k, dim d); 16 loads in flight; chain order unchanged
    const int k  = tid >> 6;            // beam 0..3
    const int dl = tid & 63;            // d within chunk
    const int d  = c * 64 + dl;
    float a = 0.f;
    const float* eb = enc + (size_t)b * SLEN * DIM + d;
    for (int s = 0; s < SLEN; s += 16) {
        float ev[16];
#pragma unroll
        for (int j = 0; j < 16; j++) ev[j] = eb[(size_t)(s + j) * DIM];
#pragma unroll
        for (int j = 0; j < 16; j++) a += p_s[k][s + j] * ev[j];
    }
    const int row = b * 4 + k;
    const int tok = (t == 1) ? SOS_TOK : g_cur[row];
    g_h[row * DIM + d] = emb[(size_t)tok * DIM + d] + a;
}

// ---------------- fused logits GEMM (round-11 exact, kk+=4) + top4/LSE + beam combine ----------------
__global__ __launch_bounds__(256) void logits_kernel(
    const float* __restrict__ Wfc, const float* __restrict__ bfc,
    float* __restrict__ out, int t)
{
    __shared__ float As[32][BKC];                       // 16 KB
    __shared__ unsigned long long s_ckey[4][64][4];     // 8 KB
    __shared__ float s_cm[4][64], s_cs[4][64];          // 2 KB
    __shared__ float s_lp[64][4];                       // 1 KB
    __shared__ int   s_tok[64][4];                      // 1 KB
    __shared__ int   s_last;

    const int tid = threadIdx.x;
    const int tx  = tid & 31;
    const int ty  = tid >> 5;        // 0..7, rows ty*4 .. ty*4+3 (local)
    const int cb  = blockIdx.x;      // column block 0..249
    const int rg  = blockIdx.y;      // row group 0..1
    const int n0  = cb * BN;
    const int n   = n0 + tx * 4;

    float acc[4][4];
#pragma unroll
    for (int i = 0; i < 4; i++)
#pragma unroll
        for (int j = 0; j < 4; j++) acc[i][j] = 0.f;

    // ---- GEMM: per-column k-chain sequential 0..511 (bit-exact) ----
    for (int kc = 0; kc < DIM / BKC; kc++) {
#pragma unroll
        for (int i = 0; i < 4; i++) {
            int f  = tid + i * 256;              // 0..1023
            int m  = f >> 5;                     // 0..31
            int k4 = (f & 31) << 2;
            *(float4*)&As[m][k4] =
                *(const float4*)&g_h[(rg * 32 + m) * DIM + kc * BKC + k4];
        }
        __syncthreads();
        const float* Bp = Wfc + (size_t)(kc * BKC) * VOCAB + n;
#pragma unroll 2
        for (int kk = 0; kk < BKC; kk += 4) {
            float4 b0 = *(const float4*)Bp; Bp += VOCAB;
            float4 b1 = *(const float4*)Bp; Bp += VOCAB;
            float4 b2 = *(const float4*)Bp; Bp += VOCAB;
            float4 b3 = *(const float4*)Bp; Bp += VOCAB;
#pragma unroll
            for (int i = 0; i < 4; i++) {
                float4 av = *(const float4*)&As[ty * 4 + i][kk];
                acc[i][0] += av.x * b0.x; acc[i][1] += av.x * b0.y;
                acc[i][2] += av.x * b0.z; acc[i][3] += av.x * b0.w;
                acc[i][0] += av.y * b1.x; acc[i][1] += av.y * b1.y;
                acc[i][2] += av.y * b1.z; acc[i][3] += av.y * b1.w;
                acc[i][0] += av.z * b2.x; acc[i][1] += av.z * b2.y;
                acc[i][2] += av.z * b2.z; acc[i][3] += av.z * b2.w;
                acc[i][0] += av.w * b3.x; acc[i][1] += av.w * b3.y;
                acc[i][2] += av.w * b3.z; acc[i][3] += av.w * b3.w;
            }
        }
        __syncthreads();
    }

    // ---- epilogue: per-row top4 + (max,sumexp) warp butterfly ----
    float4 bb = *(const float4*)&bfc[n];
#pragma unroll
    for (int i = 0; i < 4; i++) {
        const int r = rg * 32 + ty * 4 + i;
        float x0 = acc[i][0] + bb.x, x1 = acc[i][1] + bb.y;
        float x2 = acc[i][2] + bb.z, x3 = acc[i][3] + bb.w;
        float ml = fmaxf(fmaxf(x0, x1), fmaxf(x2, x3));
        float sl = __expf(x0 - ml) + __expf(x1 - ml) + __expf(x2 - ml) + __expf(x3 - ml);
        unsigned long long k0 = enc_key(x0, n);
        unsigned long long k1 = enc_key(x1, n + 1);
        unsigned long long k2 = enc_key(x2, n + 2);
        unsigned long long k3 = enc_key(x3, n + 3);
        kswap(k0, k1); kswap(k2, k3); kswap(k0, k2); kswap(k1, k3); kswap(k1, k2);
#pragma unroll
        for (int off = 16; off; off >>= 1) {
            unsigned long long b0 = __shfl_xor_sync(0xffffffffu, k0, off);
            unsigned long long b1 = __shfl_xor_sync(0xffffffffu, k1, off);
            unsigned long long b2 = __shfl_xor_sync(0xffffffffu, k2, off);
            unsigned long long b3 = __shfl_xor_sync(0xffffffffu, k3, off);
            MERGE44(k0, k1, k2, k3, b0, b1, b2, b3);
            float m2 = __shfl_xor_sync(0xffffffffu, ml, off);
            float s2 = __shfl_xor_sync(0xffffffffu, sl, off);
            float M = fmaxf(ml, m2);
            sl = sl * __expf(ml - M) + s2 * __expf(m2 - M);
            ml = M;
        }
        if (tx == 0) {
            g_pkey[r][cb][0] = k0; g_pkey[r][cb][1] = k1;
            g_pkey[r][cb][2] = k2; g_pkey[r][cb][3] = k3;
            g_pm[r][cb] = ml; g_ps[r][cb] = sl;
        }
    }

    // ---- last-block election ----
    __threadfence();
    __syncthreads();
    if (tid == 0) s_last = (atomicAdd(&g_count, 1) == NBLK_LOGITS - 1);
    __syncthreads();
    if (!s_last) return;
    __threadfence();

    // ---- merge 250 partials per row ----
    {
        const int r = tid & 63, c = tid >> 6;
        const int p0c = c * 64;
        const int p1c = (p0c + 64 < VBLKS) ? p0c + 64 : VBLKS;
        unsigned long long k0 = 0, k1 = 0, k2 = 0, k3 = 0;
        float m = -INFINITY, s = 0.f;
        for (int p = p0c; p < p1c; p++) {
            unsigned long long b0 = g_pkey[r][p][0], b1 = g_pkey[r][p][1];
            unsigned long long b2 = g_pkey[r][p][2], b3 = g_pkey[r][p][3];
            MERGE44(k0, k1, k2, k3, b0, b1, b2, b3);
            float m2 = g_pm[r][p], s2 = g_ps[r][p];
            float M = fmaxf(m, m2);
            s = s * __expf(m - M) + s2 * __expf(m2 - M);
            m = M;
        }
        s_ckey[c][r][0] = k0; s_ckey[c][r][1] = k1;
        s_ckey[c][r][2] = k2; s_ckey[c][r][3] = k3;
        s_cm[c][r] = m; s_cs[c][r] = s;
    }
    __syncthreads();
    if (tid < 64) {
        const int r = tid;
        unsigned long long k0 = s_ckey[0][r][0], k1 = s_ckey[0][r][1];
        unsigned long long k2 = s_ckey[0][r][2], k3 = s_ckey[0][r][3];
        float m = s_cm[0][r], s = s_cs[0][r];
#pragma unroll
        for (int c = 1; c < 4; c++) {
            unsigned long long b0 = s_ckey[c][r][0], b1 = s_ckey[c][r][1];
            unsigned long long b2 = s_ckey[c][r][2], b3 = s_ckey[c][r][3];
            MERGE44(k0, k1, k2, k3, b0, b1, b2, b3);
            float m2 = s_cm[c][r], s2 = s_cs[c][r];
            float M = fmaxf(m, m2);
            s = s * __expf(m - M) + s2 * __expf(m2 - M);
            m = M;
        }
        float lse = m + logf(s);
        s_lp[r][0] = dec_val(k0) - lse; s_tok[r][0] = dec_idx(k0);
        s_lp[r][1] = dec_val(k1) - lse; s_tok[r][1] = dec_idx(k1);
        s_lp[r][2] = dec_val(k2) - lse; s_tok[r][2] = dec_idx(k2);
        s_lp[r][3] = dec_val(k3) - lse; s_tok[r][3] = dec_idx(k3);
    }
    __syncthreads();

    // ---- beam init / combine (16 threads, one per batch) ----
    if (tid < 16) {
        const int b = tid;
        if (t == 1) {
            for (int k = 0; k < KBEAM; k++) {
                float lp = s_lp[b * 4][k];
                int   tk = s_tok[b * 4][k];
                g_scores[b * 4 + k] = lp;
                g_fin[b * 4 + k]    = (tk == EOS_TOK) ? 1 : 0;
                g_cur[b * 4 + k]    = tk;
                for (int pos = 0; pos < TMAX; pos++) {
                    int v2 = PAD_TOK;
                    if (pos == 0) v2 = SOS_TOK;
                    else if (pos == 1) v2 = tk;
                    g_seqs[(b * 4 + k) * TMAX + pos] = v2;
                }
            }
        } else {
            float sc[4]; int fin[4];
            for (int k = 0; k < 4; k++) {
                sc[k]  = g_scores[b * 4 + k];
                fin[k] = g_fin[b * 4 + k];
            }
            float tot[16]; int tokc[16];
            for (int k = 0; k < 4; k++) {
                for (int j = 0; j < 4; j++) {
                    float lp; int tk;
                    if (fin[k]) { lp = (j == 0) ? 0.f : NEGV; tk = PAD_TOK; }
                    else        { lp = s_lp[b * 4 + k][j]; tk = s_tok[b * 4 + k][j]; }
                    tot[k * 4 + j]  = sc[k] + lp;
                    tokc[k * 4 + j] = tk;
                }
            }
            int used[16];
            for (int i = 0; i < 16; i++) used[i] = 0;
            int selb[4], selt[4]; float selsc[4];
            for (int p = 0; p < 4; p++) {
                int best = -1; float bv = -INFINITY;
                for (int i = 0; i < 16; i++)
                    if (!used[i] && tot[i] > bv) { bv = tot[i]; best = i; }
                used[best] = 1;
                selsc[p] = bv;
                selb[p]  = best >> 2;
                selt[p]  = tokc[best];
            }
            int oldseq[4][TMAX];
            for (int k = 0; k < 4; k++)
                for (int pos = 0; pos < TMAX; pos++)
                    oldseq[k][pos] = g_seqs[(b * 4 + k) * TMAX + pos];
            for (int p = 0; p < 4; p++) {
                int bi = selb[p], tk = selt[p];
                for (int pos = 0; pos < TMAX; pos++)
                    g_seqs[(b * 4 + p) * TMAX + pos] = (pos == t) ? tk : oldseq[bi][pos];
                g_fin[b * 4 + p]    = fin[bi] | (tk == EOS_TOK);
                g_cur[b * 4 + p]    = tk;
                g_scores[b * 4 + p] = selsc[p];
            }
            if (t == TMAX - 1) {
                float bv = -INFINITY; int bi = 0;
                for (int k = 0; k < KBEAM; k++) {
                    float v2 = g_scores[b * 4 + k];
                    if (v2 > bv) { bv = v2; bi = k; }
                }
                for (int pos = 0; pos < TMAX; pos++)
                    out[b * TMAX + pos] = (float)g_seqs[(b * 4 + bi) * TMAX + pos];
                out[BATCH * TMAX + b] = bv;
            }
        }
    }
    if (tid == 0) g_count = 0;
}

// ---------------- launch ----------------
extern "C" void kernel_launch(void* const* d_in, const int* in_sizes, int n_in,
                              void* d_out, int out_size)
{
    const float* enc  = (const float*)d_in[0];
    const int*   lens = (const int*)  d_in[1];
    const float* emb  = (const float*)d_in[2];
    const float* Wq   = (const float*)d_in[3];
    const float* Wk   = (const float*)d_in[4];
    const float* Wfc  = (const float*)d_in[5];
    const float* bfc  = (const float*)d_in[6];
    float* out = (float*)d_out;

    float* p_encK;
    cudaGetSymbolAddress((void**)&p_encK, g_encK);

    // encK = enc @ Wk : [b][s][d] row-major
    sgemm_kernel<<<dim3(DIM / GBN, (BATCH * SLEN) / GBM), 256>>>(
        enc, Wk, p_encK, BATCH * SLEN, DIM, DIM);

    for (int t = 1; t < TMAX; t++) {
        q_kernel<<<64, 512>>>(emb, Wq, t);
        score_kernel<<<dim3(64, 8), 256>>>(lens);
        sctx_kernel<<<dim3(16, 8), 256>>>(enc, emb, t);
        logits_kernel<<<dim3(VBLKS, 2), 256>>>(Wfc, bfc, out, t);
    }
}